// round 15
// baseline (speedup 1.0000x reference)
#include <cuda_runtime.h>
#include <cuda_fp16.h>
#include <cstdint>
#include <cstddef>

// Problem constants
#define BQ 8192      // batch rows      (GEMM M)
#define NQ 4096      // inner dim       (GEMM K)
#define KQ 11008     // output cols     (GEMM N)
#define NG 64        // quant groups along NQ

// GEMM tiling: 128x128 CTA tile, 128 threads (4 warps, 2x2), warp tile 64x64,
// 2 CTAs/SM. R11 unrolled pipeline. Main kernel covers n-cols 0..82; the last
// 3 columns (192 tiles) run as 576 split-K(1/3) jobs accumulating atomically.
// Prep kernel also zeroes the tail strip (replaces the memset launch).
#define BM 128
#define BN 128
#define BK 64
#define NKIT (NQ / BK)            // 64 chunks per tile
#define NSTAGE 3
#define STAGE_A (BM * BK * 2)     // 16384 B
#define STAGE_B (BN * BK * 2)     // 16384 B
#define STAGE_BYTES (STAGE_A + STAGE_B)      // 32768 B
#define SMEM_TOTAL (NSTAGE * STAGE_BYTES)    // 98304 B

#define NCOL_MAIN 83              // main kernel n-columns
#define NTAIL_TILES 192           // 3 columns x 64 m-tiles
#define TAIL_SEG 21               // chunks per split-K segment (21/21/22)

// ---------------------------------------------------------------------------
// Scratch
// ---------------------------------------------------------------------------
__device__ __align__(1024) __half g_A[(size_t)BQ * NQ];
__device__ __align__(1024) __half g_W[(size_t)KQ * NQ];

__device__ __forceinline__ uint32_t smem_u32(const void* p) {
    uint32_t a;
    asm("{ .reg .u64 t; cvta.to.shared.u64 t, %1; cvt.u32.u64 %0, t; }" : "=r"(a) : "l"(p));
    return a;
}

__device__ __forceinline__ void cp_async16(uint32_t saddr, const void* gaddr) {
    asm volatile("cp.async.cg.shared.global [%0], [%1], 16;" :: "r"(saddr), "l"(gaddr) : "memory");
}

__device__ __forceinline__ uint32_t pack_half2(float a, float b) {
    __half2 h = __halves2half2(__float2half_rn(a), __float2half_rn(b));
    return *reinterpret_cast<uint32_t*>(&h);
}

// ---------------------------------------------------------------------------
// Fused prep, 4 items per thread, streaming cache hints.
// Blocks [0, XB4): g_A.  [XB4, XB4+WB4): g_W.  [XB4+WB4, +ZB): zero tail strip.
// ---------------------------------------------------------------------------
#define XB4 ((BQ * NQ / 4) / 1024)               // 8192 blocks
#define WB4 ((KQ * NQ / 4) / 1024)               // 11008 blocks
#define ZB  768                                  // strip zero blocks
#define STRIP_U4 (BQ * 96)                       // 384 floats/row = 96 uint4/row

__global__ void prep_kernel(const float* __restrict__ x, const float* __restrict__ mu1,
                            const int* __restrict__ Wq, const float* __restrict__ zeros,
                            const float* __restrict__ scales, const float* __restrict__ mu2,
                            float* __restrict__ out) {
    int b = blockIdx.x;
    if (b < XB4) {
        int base = b * 1024 + threadIdx.x;
        #pragma unroll
        for (int j = 0; j < 4; j++) {
            int idx = base + j * 256;                     // one per 4 elements of x
            int n4 = idx & (NQ / 4 - 1);
            float4 xv = __ldcs(reinterpret_cast<const float4*>(x) + idx);
            float4 mv = __ldg(reinterpret_cast<const float4*>(mu1) + n4);
            uint2 v;
            v.x = pack_half2(xv.x * mv.x, xv.y * mv.y);
            v.y = pack_half2(xv.z * mv.z, xv.w * mv.w);
            __stcs(reinterpret_cast<uint2*>(g_A) + idx, v);
        }
    } else if (b < XB4 + WB4) {
        int base = (b - XB4) * 1024 + threadIdx.x;
        #pragma unroll
        for (int j = 0; j < 4; j++) {
            int idx = base + j * 256;                     // one per 4 elements of W
            int k = idx >> 10;                            // / (NQ/4)
            int n4 = idx & 1023;
            int g = n4 >> 4;                              // (n4*4)/64
            int4 qv = __ldcs(reinterpret_cast<const int4*>(Wq) + idx);
            float z  = __ldg(zeros + k * NG + g);
            float sc = __ldg(scales + k * NG + g) * __ldg(mu2 + k);
            uint2 v;
            v.x = pack_half2(((float)qv.x - z) * sc, ((float)qv.y - z) * sc);
            v.y = pack_half2(((float)qv.z - z) * sc, ((float)qv.w - z) * sc);
            __stcs(reinterpret_cast<uint2*>(g_W) + idx, v);
        }
    } else {
        // Zero the tail strip: rows 0..BQ-1, cols NCOL_MAIN*BN .. KQ-1 (384 f32).
        int base = (b - XB4 - WB4) * 1024 + threadIdx.x;
        const uint4 zv = make_uint4(0u, 0u, 0u, 0u);
        #pragma unroll
        for (int j = 0; j < 4; j++) {
            int z = base + j * 256;                       // uint4 index in strip
            int row = z / 96;
            int c16 = z - row * 96;
            float* p = out + (size_t)row * KQ + NCOL_MAIN * BN + c16 * 4;
            __stcs(reinterpret_cast<uint4*>(p), zv);
        }
    }
}

// ---------------------------------------------------------------------------
// Shared mainloop macros (used by both GEMM kernels; reference kernel locals)
// ---------------------------------------------------------------------------
#define LOAD_FRAGS(SABASE, SBBASE, ks, buf)                                            \
do {                                                                                   \
    const uint32_t colA = (((uint32_t)(ks) * 32) + aColL) ^ xorv;                      \
    const uint32_t colB = (((uint32_t)(ks) * 32) + bColL) ^ xorv;                      \
    _Pragma("unroll")                                                                  \
    for (int mt = 0; mt < 4; mt++) {                                                   \
        uint32_t addr = (SABASE) + aRow + (uint32_t)mt * 2048u + colA;                 \
        asm volatile("ldmatrix.sync.aligned.m8n8.x4.shared.b16 {%0,%1,%2,%3}, [%4];"   \
                     : "=r"(afr[buf][mt][0]), "=r"(afr[buf][mt][1]),                   \
                       "=r"(afr[buf][mt][2]), "=r"(afr[buf][mt][3])                    \
                     : "r"(addr));                                                     \
    }                                                                                  \
    _Pragma("unroll")                                                                  \
    for (int np = 0; np < 4; np++) {                                                   \
        uint32_t addr = (SBBASE) + bRow + (uint32_t)np * 2048u + colB;                 \
        asm volatile("ldmatrix.sync.aligned.m8n8.x4.shared.b16 {%0,%1,%2,%3}, [%4];"   \
                     : "=r"(bfr[buf][np][0]), "=r"(bfr[buf][np][1]),                   \
                       "=r"(bfr[buf][np][2]), "=r"(bfr[buf][np][3])                    \
                     : "r"(addr));                                                     \
    }                                                                                  \
} while (0)

#define MMA_STEP(buf)                                                                  \
do {                                                                                   \
    _Pragma("unroll")                                                                  \
    for (int mt = 0; mt < 4; mt++) {                                                   \
        _Pragma("unroll")                                                              \
        for (int nt = 0; nt < 8; nt++) {                                               \
            const uint32_t b0 = bfr[buf][nt >> 1][(nt & 1) * 2];                       \
            const uint32_t b1 = bfr[buf][nt >> 1][(nt & 1) * 2 + 1];                   \
            asm volatile(                                                              \
                "mma.sync.aligned.m16n8k16.row.col.f32.f16.f16.f32 "                   \
                "{%0,%1,%2,%3}, {%4,%5,%6,%7}, {%8,%9}, {%0,%1,%2,%3};"                \
                : "+f"(acc[mt][nt][0]), "+f"(acc[mt][nt][1]),                          \
                  "+f"(acc[mt][nt][2]), "+f"(acc[mt][nt][3])                           \
                : "r"(afr[buf][mt][0]), "r"(afr[buf][mt][1]),                          \
                  "r"(afr[buf][mt][2]), "r"(afr[buf][mt][3]),                          \
                  "r"(b0), "r"(b1));                                                   \
        }                                                                              \
    }                                                                                  \
} while (0)

#define GEMM_SETUP()                                                                   \
    extern __shared__ __align__(1024) char smem[];                                     \
    const uint32_t sb = smem_u32(smem);                                                \
    const int tid = threadIdx.x;                                                       \
    const int lane = tid & 31, wid = tid >> 5;                                         \
    const int wm = wid >> 1, wn = wid & 1;                                             \
    const int lrow = tid >> 3, lseg = tid & 7;                                         \
    const uint32_t swb = ((uint32_t)(lrow * 128 + lseg * 16)) ^                        \
                         (((uint32_t)lrow & 7u) << 4);                                 \
    const char* gA = reinterpret_cast<const char*>(g_A) +                              \
                     ((size_t)(mBase + lrow) * NQ + (size_t)lseg * 8) * 2;             \
    const char* gB = reinterpret_cast<const char*>(g_W) +                              \
                     ((size_t)(nBase + lrow) * NQ + (size_t)lseg * 8) * 2;             \
    auto load_stage = [&](uint32_t stOff_, int kc_) {                                  \
        uint32_t dA = sb + stOff_ + swb;                                               \
        const char* srcA = gA + (size_t)kc_ * 128;                                     \
        _Pragma("unroll")                                                              \
        for (int i = 0; i < 8; i++)                                                    \
            cp_async16(dA + (uint32_t)i * 2048u, srcA + (size_t)i * 16 * (NQ * 2));    \
        uint32_t dB = dA + STAGE_A;                                                    \
        const char* srcB = gB + (size_t)kc_ * 128;                                     \
        _Pragma("unroll")                                                              \
        for (int i = 0; i < 8; i++)                                                    \
            cp_async16(dB + (uint32_t)i * 2048u, srcB + (size_t)i * 16 * (NQ * 2));    \
        asm volatile("cp.async.commit_group;" ::: "memory");                           \
    };                                                                                 \
    float acc[4][8][4];                                                                \
    _Pragma("unroll")                                                                  \
    for (int mt = 0; mt < 4; mt++)                                                     \
        for (int nt = 0; nt < 8; nt++)                                                 \
            for (int q = 0; q < 4; q++) acc[mt][nt][q] = 0.0f;                         \
    const uint32_t xorv = ((uint32_t)lane & 7u) << 4;                                  \
    const uint32_t aRow = (uint32_t)(wm * 64 + (lane & 15)) * 128;                     \
    const uint32_t aColL = ((uint32_t)(lane >> 4)) << 4;                               \
    const uint32_t bRowOff = (uint32_t)((lane & 7) + (((lane >> 4) & 1) << 3));        \
    const uint32_t bRow = ((uint32_t)wn * 64 + bRowOff) * 128;                         \
    const uint32_t bColL = ((uint32_t)((lane >> 3) & 1)) << 4;                         \
    uint32_t afr[2][4][4], bfr[2][4][4];

// ---------------------------------------------------------------------------
// Main GEMM: n-cols 0..82, full K, unrolled x3 with compile-time stages.
// ---------------------------------------------------------------------------
__global__ void __launch_bounds__(128, 2) gemm_kernel(float* __restrict__ out) {
    const int mBase = blockIdx.x * BM;                   // m fast-varying
    const int nBase = blockIdx.y * BN;
    GEMM_SETUP();

    #define BODY_FULL(SOFF, NOFF, WOFF)                                                \
    do {                                                                               \
        const uint32_t sA = sb + (SOFF), sBs = sA + STAGE_A;                           \
        LOAD_FRAGS(sA, sBs, 1, 1);                                                     \
        MMA_STEP(0);                                                                   \
        LOAD_FRAGS(sA, sBs, 2, 0);                                                     \
        MMA_STEP(1);                                                                   \
        LOAD_FRAGS(sA, sBs, 3, 1);                                                     \
        MMA_STEP(0);                                                                   \
        load_stage((WOFF), kc);                                                        \
        kc++;                                                                          \
        asm volatile("cp.async.wait_group 1;" ::: "memory");                           \
        __syncthreads();                                                               \
        LOAD_FRAGS(sb + (NOFF), sb + (NOFF) + STAGE_A, 0, 0);                          \
        MMA_STEP(1);                                                                   \
    } while (0)

    #define BODY_NOLOAD(SOFF, NOFF)                                                   \
    do {                                                                               \
        const uint32_t sA = sb + (SOFF), sBs = sA + STAGE_A;                           \
        LOAD_FRAGS(sA, sBs, 1, 1);                                                     \
        MMA_STEP(0);                                                                   \
        LOAD_FRAGS(sA, sBs, 2, 0);                                                     \
        MMA_STEP(1);                                                                   \
        LOAD_FRAGS(sA, sBs, 3, 1);                                                     \
        MMA_STEP(0);                                                                   \
        asm volatile("cp.async.wait_group 0;" ::: "memory");                           \
        __syncthreads();                                                               \
        LOAD_FRAGS(sb + (NOFF), sb + (NOFF) + STAGE_A, 0, 0);                          \
        MMA_STEP(1);                                                                   \
    } while (0)

    #define BODY_LAST(SOFF)                                                            \
    do {                                                                               \
        const uint32_t sA = sb + (SOFF), sBs = sA + STAGE_A;                           \
        LOAD_FRAGS(sA, sBs, 1, 1);                                                     \
        MMA_STEP(0);                                                                   \
        LOAD_FRAGS(sA, sBs, 2, 0);                                                     \
        MMA_STEP(1);                                                                   \
        LOAD_FRAGS(sA, sBs, 3, 1);                                                     \
        MMA_STEP(0);                                                                   \
        MMA_STEP(1);                                                                   \
    } while (0)

    // Prologue
    load_stage(0u, 0);
    load_stage(STAGE_BYTES, 1);
    asm volatile("cp.async.wait_group 1;" ::: "memory");
    __syncthreads();
    LOAD_FRAGS(sb, sb + STAGE_A, 0, 0);

    int kc = 2;
    for (int j = 0; j < 20; j++) {
        BODY_FULL(0u, STAGE_BYTES, 2u * STAGE_BYTES);
        BODY_FULL(STAGE_BYTES, 2u * STAGE_BYTES, 0u);
        BODY_FULL(2u * STAGE_BYTES, 0u, STAGE_BYTES);
    }
    BODY_FULL(0u, STAGE_BYTES, 2u * STAGE_BYTES);         // loads kc=62
    BODY_FULL(STAGE_BYTES, 2u * STAGE_BYTES, 0u);         // loads kc=63
    BODY_NOLOAD(2u * STAGE_BYTES, 0u);                    // it=62
    BODY_LAST(0u);                                        // it=63

    #undef BODY_FULL
    #undef BODY_NOLOAD
    #undef BODY_LAST

    // Epilogue: fp32 stores
    const int mRow = mBase + wm * 64 + (lane >> 2);
    const int nCol = nBase + wn * 64 + (lane & 3) * 2;
    #pragma unroll
    for (int mt = 0; mt < 4; mt++) {
        #pragma unroll
        for (int nt = 0; nt < 8; nt++) {
            float* p = out + (size_t)(mRow + mt * 16) * KQ + (nCol + nt * 8);
            *reinterpret_cast<float2*>(p) = make_float2(acc[mt][nt][0], acc[mt][nt][1]);
            *reinterpret_cast<float2*>(p + (size_t)8 * KQ) =
                make_float2(acc[mt][nt][2], acc[mt][nt][3]);
        }
    }
}

// ---------------------------------------------------------------------------
// Tail GEMM: n-cols 83..85, split-K/3 (segments 21/21/22 chunks), atomicAdd
// into the prep-zeroed strip. Dynamic-stage pipeline (R10 structure).
// ---------------------------------------------------------------------------
__global__ void __launch_bounds__(128, 2) gemm_tail_kernel(float* __restrict__ out) {
    const int bid = blockIdx.x;                          // 0..575
    const int seg = bid / NTAIL_TILES;                   // 0..2
    const int t = bid - seg * NTAIL_TILES;               // 0..191
    const int mBase = (t & 63) * BM;
    const int nBase = (NCOL_MAIN + (t >> 6)) * BN;
    const int kstart = seg * TAIL_SEG;
    const int nk = (seg == 2) ? (NKIT - 2 * TAIL_SEG) : TAIL_SEG;   // 21/21/22
    GEMM_SETUP();

    // Prologue
    load_stage(0u, kstart);
    load_stage(STAGE_BYTES, kstart + 1);
    asm volatile("cp.async.wait_group 1;" ::: "memory");
    __syncthreads();
    LOAD_FRAGS(sb, sb + STAGE_A, 0, 0);

    uint32_t stOff = 0;
    int kc = kstart + 2;
    const int kend = kstart + nk;

    for (int it = 0; it < nk; it++) {
        const uint32_t sA = sb + stOff, sBs = sA + STAGE_A;
        uint32_t nOff = stOff + STAGE_BYTES;
        if (nOff == NSTAGE * STAGE_BYTES) nOff = 0;
        uint32_t wOff = nOff + STAGE_BYTES;
        if (wOff == NSTAGE * STAGE_BYTES) wOff = 0;

        LOAD_FRAGS(sA, sBs, 1, 1);
        MMA_STEP(0);
        LOAD_FRAGS(sA, sBs, 2, 0);
        MMA_STEP(1);
        LOAD_FRAGS(sA, sBs, 3, 1);
        MMA_STEP(0);

        if (it + 1 < nk) {
            if (kc < kend) {
                load_stage(wOff, kc);
                kc++;
            } else {
                asm volatile("cp.async.commit_group;" ::: "memory");
            }
            asm volatile("cp.async.wait_group 1;" ::: "memory");
            __syncthreads();
            LOAD_FRAGS(sb + nOff, sb + nOff + STAGE_A, 0, 0);
        }
        MMA_STEP(1);
        stOff = nOff;
    }

    // Epilogue: atomic accumulation (strip zeroed by prep)
    const int mRow = mBase + wm * 64 + (lane >> 2);
    const int nCol = nBase + wn * 64 + (lane & 3) * 2;
    #pragma unroll
    for (int mt = 0; mt < 4; mt++) {
        #pragma unroll
        for (int nt = 0; nt < 8; nt++) {
            float* p = out + (size_t)(mRow + mt * 16) * KQ + (nCol + nt * 8);
            atomicAdd(p, acc[mt][nt][0]);
            atomicAdd(p + 1, acc[mt][nt][1]);
            atomicAdd(p + (size_t)8 * KQ, acc[mt][nt][2]);
            atomicAdd(p + (size_t)8 * KQ + 1, acc[mt][nt][3]);
        }
    }
}

// ---------------------------------------------------------------------------
// Launch
// ---------------------------------------------------------------------------
extern "C" void kernel_launch(void* const* d_in, const int* in_sizes, int n_in,
                              void* d_out, int out_size) {
    const float* x      = (const float*)d_in[0];
    const int*   Wq     = (const int*)d_in[1];
    const float* zeros  = (const float*)d_in[2];
    const float* scales = (const float*)d_in[3];
    const float* mu1    = (const float*)d_in[4];
    const float* mu2    = (const float*)d_in[5];
    float* out = (float*)d_out;

    cudaFuncSetAttribute(gemm_kernel, cudaFuncAttributeMaxDynamicSharedMemorySize, SMEM_TOTAL);
    cudaFuncSetAttribute(gemm_tail_kernel, cudaFuncAttributeMaxDynamicSharedMemorySize, SMEM_TOTAL);

    prep_kernel<<<XB4 + WB4 + ZB, 256>>>(x, mu1, Wq, zeros, scales, mu2, out);

    dim3 grid(BQ / BM, NCOL_MAIN);                       // (64, 83), m fast-varying
    gemm_kernel<<<grid, 128, SMEM_TOTAL>>>(out);

    gemm_tail_kernel<<<3 * NTAIL_TILES, 128, SMEM_TOTAL>>>(out);
}

// round 16
// speedup vs baseline: 1.0122x; 1.0122x over previous
#include <cuda_runtime.h>
#include <cuda_fp16.h>
#include <cstdint>
#include <cstddef>

// Problem constants
#define BQ 8192      // batch rows      (GEMM M)
#define NQ 4096      // inner dim       (GEMM K)
#define KQ 11008     // output cols     (GEMM N)
#define NG 64        // quant groups along NQ

// GEMM tiling: 128x128 CTA tile, 128 threads (4 warps, 2x2), warp tile 64x64,
// 2 CTAs/SM. Single merged launch: 5312 full-K main tiles (n-cols 0..82)
// followed by 576 split-K/3 tail jobs (n-cols 83..85) that backfill the
// scheduler slots freed by main's draining last wave.
#define BM 128
#define BN 128
#define BK 64
#define NKIT (NQ / BK)            // 64 chunks per tile
#define NSTAGE 3
#define STAGE_A (BM * BK * 2)     // 16384 B
#define STAGE_B (BN * BK * 2)     // 16384 B
#define STAGE_BYTES (STAGE_A + STAGE_B)      // 32768 B
#define SMEM_TOTAL (NSTAGE * STAGE_BYTES)    // 98304 B

#define NCOL_MAIN 83              // main n-columns
#define NMAIN_TILES (64 * NCOL_MAIN)         // 5312
#define NTAIL_TILES 192           // 3 columns x 64 m-tiles
#define TAIL_SEG 21               // chunks per split-K segment (21/21/22)

// ---------------------------------------------------------------------------
// Scratch
// ---------------------------------------------------------------------------
__device__ __align__(1024) __half g_A[(size_t)BQ * NQ];
__device__ __align__(1024) __half g_W[(size_t)KQ * NQ];

__device__ __forceinline__ uint32_t smem_u32(const void* p) {
    uint32_t a;
    asm("{ .reg .u64 t; cvta.to.shared.u64 t, %1; cvt.u32.u64 %0, t; }" : "=r"(a) : "l"(p));
    return a;
}

__device__ __forceinline__ void cp_async16(uint32_t saddr, const void* gaddr) {
    asm volatile("cp.async.cg.shared.global [%0], [%1], 16;" :: "r"(saddr), "l"(gaddr) : "memory");
}

__device__ __forceinline__ uint32_t pack_half2(float a, float b) {
    __half2 h = __halves2half2(__float2half_rn(a), __float2half_rn(b));
    return *reinterpret_cast<uint32_t*>(&h);
}

// ---------------------------------------------------------------------------
// Fused prep (plain loads/stores — R14's streaming hints regressed DRAM%).
// Blocks [0, XB4): g_A.  [XB4, XB4+WB4): g_W.  [XB4+WB4, +ZB): zero tail strip.
// ---------------------------------------------------------------------------
#define XB4 ((BQ * NQ / 4) / 1024)               // 8192 blocks
#define WB4 ((KQ * NQ / 4) / 1024)               // 11008 blocks
#define ZB  768                                  // strip zero blocks

__global__ void prep_kernel(const float* __restrict__ x, const float* __restrict__ mu1,
                            const int* __restrict__ Wq, const float* __restrict__ zeros,
                            const float* __restrict__ scales, const float* __restrict__ mu2,
                            float* __restrict__ out) {
    int b = blockIdx.x;
    if (b < XB4) {
        int base = b * 1024 + threadIdx.x;
        #pragma unroll
        for (int j = 0; j < 4; j++) {
            int idx = base + j * 256;                     // one per 4 elements of x
            int n4 = idx & (NQ / 4 - 1);
            float4 xv = reinterpret_cast<const float4*>(x)[idx];
            float4 mv = __ldg(reinterpret_cast<const float4*>(mu1) + n4);
            uint2 v;
            v.x = pack_half2(xv.x * mv.x, xv.y * mv.y);
            v.y = pack_half2(xv.z * mv.z, xv.w * mv.w);
            reinterpret_cast<uint2*>(g_A)[idx] = v;
        }
    } else if (b < XB4 + WB4) {
        int base = (b - XB4) * 1024 + threadIdx.x;
        #pragma unroll
        for (int j = 0; j < 4; j++) {
            int idx = base + j * 256;                     // one per 4 elements of W
            int k = idx >> 10;                            // / (NQ/4)
            int n4 = idx & 1023;
            int g = n4 >> 4;                              // (n4*4)/64
            int4 qv = reinterpret_cast<const int4*>(Wq)[idx];
            float z  = __ldg(zeros + k * NG + g);
            float sc = __ldg(scales + k * NG + g) * __ldg(mu2 + k);
            uint2 v;
            v.x = pack_half2(((float)qv.x - z) * sc, ((float)qv.y - z) * sc);
            v.y = pack_half2(((float)qv.z - z) * sc, ((float)qv.w - z) * sc);
            reinterpret_cast<uint2*>(g_W)[idx] = v;
        }
    } else {
        // Zero the tail strip: rows 0..BQ-1, cols NCOL_MAIN*BN .. KQ-1 (384 f32).
        int base = (b - XB4 - WB4) * 1024 + threadIdx.x;
        const uint4 zv = make_uint4(0u, 0u, 0u, 0u);
        #pragma unroll
        for (int j = 0; j < 4; j++) {
            int z = base + j * 256;                       // uint4 index in strip
            int row = z / 96;
            int c16 = z - row * 96;
            float* p = out + (size_t)row * KQ + NCOL_MAIN * BN + c16 * 4;
            *reinterpret_cast<uint4*>(p) = zv;
        }
    }
}

// ---------------------------------------------------------------------------
// Shared mainloop macros
// ---------------------------------------------------------------------------
#define LOAD_FRAGS(SABASE, SBBASE, ks, buf)                                            \
do {                                                                                   \
    const uint32_t colA = (((uint32_t)(ks) * 32) + aColL) ^ xorv;                      \
    const uint32_t colB = (((uint32_t)(ks) * 32) + bColL) ^ xorv;                      \
    _Pragma("unroll")                                                                  \
    for (int mt = 0; mt < 4; mt++) {                                                   \
        uint32_t addr = (SABASE) + aRow + (uint32_t)mt * 2048u + colA;                 \
        asm volatile("ldmatrix.sync.aligned.m8n8.x4.shared.b16 {%0,%1,%2,%3}, [%4];"   \
                     : "=r"(afr[buf][mt][0]), "=r"(afr[buf][mt][1]),                   \
                       "=r"(afr[buf][mt][2]), "=r"(afr[buf][mt][3])                    \
                     : "r"(addr));                                                     \
    }                                                                                  \
    _Pragma("unroll")                                                                  \
    for (int np = 0; np < 4; np++) {                                                   \
        uint32_t addr = (SBBASE) + bRow + (uint32_t)np * 2048u + colB;                 \
        asm volatile("ldmatrix.sync.aligned.m8n8.x4.shared.b16 {%0,%1,%2,%3}, [%4];"   \
                     : "=r"(bfr[buf][np][0]), "=r"(bfr[buf][np][1]),                   \
                       "=r"(bfr[buf][np][2]), "=r"(bfr[buf][np][3])                    \
                     : "r"(addr));                                                     \
    }                                                                                  \
} while (0)

#define MMA_STEP(buf)                                                                  \
do {                                                                                   \
    _Pragma("unroll")                                                                  \
    for (int mt = 0; mt < 4; mt++) {                                                   \
        _Pragma("unroll")                                                              \
        for (int nt = 0; nt < 8; nt++) {                                               \
            const uint32_t b0 = bfr[buf][nt >> 1][(nt & 1) * 2];                       \
            const uint32_t b1 = bfr[buf][nt >> 1][(nt & 1) * 2 + 1];                   \
            asm volatile(                                                              \
                "mma.sync.aligned.m16n8k16.row.col.f32.f16.f16.f32 "                   \
                "{%0,%1,%2,%3}, {%4,%5,%6,%7}, {%8,%9}, {%0,%1,%2,%3};"                \
                : "+f"(acc[mt][nt][0]), "+f"(acc[mt][nt][1]),                          \
                  "+f"(acc[mt][nt][2]), "+f"(acc[mt][nt][3])                           \
                : "r"(afr[buf][mt][0]), "r"(afr[buf][mt][1]),                          \
                  "r"(afr[buf][mt][2]), "r"(afr[buf][mt][3]),                          \
                  "r"(b0), "r"(b1));                                                   \
        }                                                                              \
    }                                                                                  \
} while (0)

#define GEMM_SETUP()                                                                   \
    const int tid = threadIdx.x;                                                       \
    const int lane = tid & 31, wid = tid >> 5;                                         \
    const int wm = wid >> 1, wn = wid & 1;                                             \
    const int lrow = tid >> 3, lseg = tid & 7;                                         \
    const uint32_t swb = ((uint32_t)(lrow * 128 + lseg * 16)) ^                        \
                         (((uint32_t)lrow & 7u) << 4);                                 \
    const char* gA = reinterpret_cast<const char*>(g_A) +                              \
                     ((size_t)(mBase + lrow) * NQ + (size_t)lseg * 8) * 2;             \
    const char* gB = reinterpret_cast<const char*>(g_W) +                              \
                     ((size_t)(nBase + lrow) * NQ + (size_t)lseg * 8) * 2;             \
    auto load_stage = [&](uint32_t stOff_, int kc_) {                                  \
        uint32_t dA = sb + stOff_ + swb;                                               \
        const char* srcA = gA + (size_t)kc_ * 128;                                     \
        _Pragma("unroll")                                                              \
        for (int i = 0; i < 8; i++)                                                    \
            cp_async16(dA + (uint32_t)i * 2048u, srcA + (size_t)i * 16 * (NQ * 2));    \
        uint32_t dB = dA + STAGE_A;                                                    \
        const char* srcB = gB + (size_t)kc_ * 128;                                     \
        _Pragma("unroll")                                                              \
        for (int i = 0; i < 8; i++)                                                    \
            cp_async16(dB + (uint32_t)i * 2048u, srcB + (size_t)i * 16 * (NQ * 2));    \
        asm volatile("cp.async.commit_group;" ::: "memory");                           \
    };                                                                                 \
    float acc[4][8][4];                                                                \
    _Pragma("unroll")                                                                  \
    for (int mt = 0; mt < 4; mt++)                                                     \
        for (int nt = 0; nt < 8; nt++)                                                 \
            for (int q = 0; q < 4; q++) acc[mt][nt][q] = 0.0f;                         \
    const uint32_t xorv = ((uint32_t)lane & 7u) << 4;                                  \
    const uint32_t aRow = (uint32_t)(wm * 64 + (lane & 15)) * 128;                     \
    const uint32_t aColL = ((uint32_t)(lane >> 4)) << 4;                               \
    const uint32_t bRowOff = (uint32_t)((lane & 7) + (((lane >> 4) & 1) << 3));        \
    const uint32_t bRow = ((uint32_t)wn * 64 + bRowOff) * 128;                         \
    const uint32_t bColL = ((uint32_t)((lane >> 3) & 1)) << 4;                         \
    uint32_t afr[2][4][4], bfr[2][4][4];

// ---------------------------------------------------------------------------
// Merged GEMM: blocks [0, NMAIN_TILES) = full-K main tiles (m fast-varying);
// blocks [NMAIN_TILES, +576) = split-K/3 tail jobs (atomicAdd epilogue).
// ---------------------------------------------------------------------------
__global__ void __launch_bounds__(128, 2) gemm_all_kernel(float* __restrict__ out) {
    extern __shared__ __align__(1024) char smem[];
    const uint32_t sb = smem_u32(smem);
    const int bid = blockIdx.x;

    if (bid < NMAIN_TILES) {
        // ---- main path: full K, unrolled x3 with compile-time stages ----
        const int mBase = (bid & 63) * BM;               // m fast-varying
        const int nBase = (bid >> 6) * BN;
        GEMM_SETUP();

        #define BODY_FULL(SOFF, NOFF, WOFF)                                            \
        do {                                                                           \
            const uint32_t sA = sb + (SOFF), sBs = sA + STAGE_A;                       \
            LOAD_FRAGS(sA, sBs, 1, 1);                                                 \
            MMA_STEP(0);                                                               \
            LOAD_FRAGS(sA, sBs, 2, 0);                                                 \
            MMA_STEP(1);                                                               \
            LOAD_FRAGS(sA, sBs, 3, 1);                                                 \
            MMA_STEP(0);                                                               \
            load_stage((WOFF), kc);                                                    \
            kc++;                                                                      \
            asm volatile("cp.async.wait_group 1;" ::: "memory");                       \
            __syncthreads();                                                           \
            LOAD_FRAGS(sb + (NOFF), sb + (NOFF) + STAGE_A, 0, 0);                      \
            MMA_STEP(1);                                                               \
        } while (0)

        #define BODY_NOLOAD(SOFF, NOFF)                                                \
        do {                                                                           \
            const uint32_t sA = sb + (SOFF), sBs = sA + STAGE_A;                       \
            LOAD_FRAGS(sA, sBs, 1, 1);                                                 \
            MMA_STEP(0);                                                               \
            LOAD_FRAGS(sA, sBs, 2, 0);                                                 \
            MMA_STEP(1);                                                               \
            LOAD_FRAGS(sA, sBs, 3, 1);                                                 \
            MMA_STEP(0);                                                               \
            asm volatile("cp.async.wait_group 0;" ::: "memory");                       \
            __syncthreads();                                                           \
            LOAD_FRAGS(sb + (NOFF), sb + (NOFF) + STAGE_A, 0, 0);                      \
            MMA_STEP(1);                                                               \
        } while (0)

        #define BODY_LAST(SOFF)                                                        \
        do {                                                                           \
            const uint32_t sA = sb + (SOFF), sBs = sA + STAGE_A;                       \
            LOAD_FRAGS(sA, sBs, 1, 1);                                                 \
            MMA_STEP(0);                                                               \
            LOAD_FRAGS(sA, sBs, 2, 0);                                                 \
            MMA_STEP(1);                                                               \
            LOAD_FRAGS(sA, sBs, 3, 1);                                                 \
            MMA_STEP(0);                                                               \
            MMA_STEP(1);                                                               \
        } while (0)

        load_stage(0u, 0);
        load_stage(STAGE_BYTES, 1);
        asm volatile("cp.async.wait_group 1;" ::: "memory");
        __syncthreads();
        LOAD_FRAGS(sb, sb + STAGE_A, 0, 0);

        int kc = 2;
        for (int j = 0; j < 20; j++) {
            BODY_FULL(0u, STAGE_BYTES, 2u * STAGE_BYTES);
            BODY_FULL(STAGE_BYTES, 2u * STAGE_BYTES, 0u);
            BODY_FULL(2u * STAGE_BYTES, 0u, STAGE_BYTES);
        }
        BODY_FULL(0u, STAGE_BYTES, 2u * STAGE_BYTES);     // loads kc=62
        BODY_FULL(STAGE_BYTES, 2u * STAGE_BYTES, 0u);     // loads kc=63
        BODY_NOLOAD(2u * STAGE_BYTES, 0u);                // it=62
        BODY_LAST(0u);                                    // it=63

        #undef BODY_FULL
        #undef BODY_NOLOAD
        #undef BODY_LAST

        const int mRow = mBase + wm * 64 + (lane >> 2);
        const int nCol = nBase + wn * 64 + (lane & 3) * 2;
        #pragma unroll
        for (int mt = 0; mt < 4; mt++) {
            #pragma unroll
            for (int nt = 0; nt < 8; nt++) {
                float* p = out + (size_t)(mRow + mt * 16) * KQ + (nCol + nt * 8);
                *reinterpret_cast<float2*>(p) =
                    make_float2(acc[mt][nt][0], acc[mt][nt][1]);
                *reinterpret_cast<float2*>(p + (size_t)8 * KQ) =
                    make_float2(acc[mt][nt][2], acc[mt][nt][3]);
            }
        }
    } else {
        // ---- tail path: split-K/3 (21/21/22 chunks), atomic epilogue ----
        const int bt = bid - NMAIN_TILES;                // 0..575
        const int seg = bt / NTAIL_TILES;                // 0..2
        const int t = bt - seg * NTAIL_TILES;            // 0..191
        const int mBase = (t & 63) * BM;
        const int nBase = (NCOL_MAIN + (t >> 6)) * BN;
        const int kstart = seg * TAIL_SEG;
        const int nk = (seg == 2) ? (NKIT - 2 * TAIL_SEG) : TAIL_SEG;
        GEMM_SETUP();

        load_stage(0u, kstart);
        load_stage(STAGE_BYTES, kstart + 1);
        asm volatile("cp.async.wait_group 1;" ::: "memory");
        __syncthreads();
        LOAD_FRAGS(sb, sb + STAGE_A, 0, 0);

        uint32_t stOff = 0;
        int kc = kstart + 2;
        const int kend = kstart + nk;

        for (int it = 0; it < nk; it++) {
            const uint32_t sA = sb + stOff, sBs = sA + STAGE_A;
            uint32_t nOff = stOff + STAGE_BYTES;
            if (nOff == NSTAGE * STAGE_BYTES) nOff = 0;
            uint32_t wOff = nOff + STAGE_BYTES;
            if (wOff == NSTAGE * STAGE_BYTES) wOff = 0;

            LOAD_FRAGS(sA, sBs, 1, 1);
            MMA_STEP(0);
            LOAD_FRAGS(sA, sBs, 2, 0);
            MMA_STEP(1);
            LOAD_FRAGS(sA, sBs, 3, 1);
            MMA_STEP(0);

            if (it + 1 < nk) {
                if (kc < kend) {
                    load_stage(wOff, kc);
                    kc++;
                } else {
                    asm volatile("cp.async.commit_group;" ::: "memory");
                }
                asm volatile("cp.async.wait_group 1;" ::: "memory");
                __syncthreads();
                LOAD_FRAGS(sb + nOff, sb + nOff + STAGE_A, 0, 0);
            }
            MMA_STEP(1);
            stOff = nOff;
        }

        const int mRow = mBase + wm * 64 + (lane >> 2);
        const int nCol = nBase + wn * 64 + (lane & 3) * 2;
        #pragma unroll
        for (int mt = 0; mt < 4; mt++) {
            #pragma unroll
            for (int nt = 0; nt < 8; nt++) {
                float* p = out + (size_t)(mRow + mt * 16) * KQ + (nCol + nt * 8);
                atomicAdd(p, acc[mt][nt][0]);
                atomicAdd(p + 1, acc[mt][nt][1]);
                atomicAdd(p + (size_t)8 * KQ, acc[mt][nt][2]);
                atomicAdd(p + (size_t)8 * KQ + 1, acc[mt][nt][3]);
            }
        }
    }
}

// ---------------------------------------------------------------------------
// Launch
// ---------------------------------------------------------------------------
extern "C" void kernel_launch(void* const* d_in, const int* in_sizes, int n_in,
                              void* d_out, int out_size) {
    const float* x      = (const float*)d_in[0];
    const int*   Wq     = (const int*)d_in[1];
    const float* zeros  = (const float*)d_in[2];
    const float* scales = (const float*)d_in[3];
    const float* mu1    = (const float*)d_in[4];
    const float* mu2    = (const float*)d_in[5];
    float* out = (float*)d_out;

    cudaFuncSetAttribute(gemm_all_kernel, cudaFuncAttributeMaxDynamicSharedMemorySize, SMEM_TOTAL);

    prep_kernel<<<XB4 + WB4 + ZB, 256>>>(x, mu1, Wq, zeros, scales, mu2, out);

    gemm_all_kernel<<<NMAIN_TILES + 3 * NTAIL_TILES, 128, SMEM_TOTAL>>>(out);
}